// round 15
// baseline (speedup 1.0000x reference)
#include <cuda_runtime.h>
#include <cstdint>

#define NN    8192
#define FIN   128
#define FOUT  64
#define ALPHA 0.2f
#define LOG2E 1.4426950408889634f

#define TI    128
#define SPLIT 4
#define JH    (NN/SPLIT)   // 2048
#define KC    32
#define NCH   (JH/KC)      // 64
#define NSTAGE 4
#define NSTAGE_LOG2 2

#define NTHREADS 288       // 8 consumer warps + 1 producer warp

#define B_STRIDE 40        // halves per B row (32 + pad); word-stride 20 -> conflict-free
#define B_BUF  (FOUT*B_STRIDE*2)        // 5120
#define EF_BUF 256                      // 128 used
#define STAGE_BYTES (B_BUF + EF_BUF)    // 5376 (128-aligned)
#define MBAR_OFF   (NSTAGE*STAGE_BYTES) // 21504
#define GAT_SMEM   (MBAR_OFF + NSTAGE*16 + 256)

// ---------------- device scratch ----------------
__device__ __align__(256) uint16_t g_hT16[(size_t)FOUT * NN];  // h^T fp16 [f][node]
__device__ __align__(256) uint2 g_EF1p[NN];     // {E1 dup f16x2, F1 dup f16x2}
__device__ __align__(256) uint2 g_E2Fp[NN/2];   // {E2 pair f16x2, F2 pair f16x2}
__device__ float  g_part[SPLIT][(size_t)NN * FOUT];
__device__ float  g_wsum[SPLIT][NN];
__device__ int    g_cnt[NN / TI];

// ---------------- helpers ----------------
__device__ __forceinline__ float ex2f(float x) {
    float r; asm("ex2.approx.ftz.f32 %0, %1;" : "=f"(r) : "f"(x)); return r;
}
__device__ __forceinline__ uint32_t smem_u32(const void* p) {
    uint32_t a;
    asm("{ .reg .u64 t; cvta.to.shared.u64 t, %1; cvt.u32.u64 %0, t; }" : "=r"(a) : "l"(p));
    return a;
}
__device__ __forceinline__ uint16_t f2h(float x) {
    uint16_t r; asm("cvt.rn.f16.f32 %0, %1;" : "=h"(r) : "f"(x)); return r;
}
__device__ __forceinline__ uint32_t pkh2(float lo, float hi) {
    uint32_t r; asm("cvt.rn.f16x2.f32 %0, %1, %2;" : "=r"(r) : "f"(hi), "f"(lo)); return r;
}
__device__ __forceinline__ uint32_t hmul2(uint32_t a, uint32_t b) {
    uint32_t r; asm("mul.f16x2 %0, %1, %2;" : "=r"(r) : "r"(a), "r"(b)); return r;
}
__device__ __forceinline__ uint32_t hmax2(uint32_t a, uint32_t b) {
    uint32_t r; asm("max.f16x2 %0, %1, %2;" : "=r"(r) : "r"(a), "r"(b)); return r;
}
__device__ __forceinline__ uint32_t wpair(uint32_t e1E, uint32_t e1F,
                                          uint32_t e2, uint32_t f2,
                                          int ax, int ay) {
    const uint32_t m = (uint32_t)ax * 0x3C00u + (uint32_t)ay * 0x3C000000u;
    return hmul2(hmax2(hmul2(e1E, e2), hmul2(e1F, f2)), m);
}
// streaming (evict-first) int2 global load
__device__ __forceinline__ int2 ldcs2(const int* p) {
    int2 v;
    asm volatile("ld.global.cs.v2.u32 {%0,%1}, [%2];" : "=r"(v.x), "=r"(v.y) : "l"(p));
    return v;
}

#define CP16(dst, src) \
    asm volatile("cp.async.cg.shared.global [%0], [%1], 16;" :: "r"(dst), "l"(src) : "memory")

// mbarrier ops
#define MBAR_INIT(mb, cnt) \
    asm volatile("mbarrier.init.shared.b64 [%0], %1;" :: "r"((uint32_t)(mb)), "r"((uint32_t)(cnt)) : "memory")
#define MBAR_ARRIVE(mb) \
    asm volatile("mbarrier.arrive.shared.b64 _, [%0];" :: "r"((uint32_t)(mb)) : "memory")
#define CPASYNC_MBAR_ARRIVE(mb) \
    asm volatile("cp.async.mbarrier.arrive.noinc.shared.b64 [%0];" :: "r"((uint32_t)(mb)) : "memory")
#define MBAR_WAIT(mb, parity) do { \
    uint32_t _m = (uint32_t)(mb); uint32_t _p = (uint32_t)(parity); uint32_t _d; \
    asm volatile("{\n\t.reg .pred p;\n\tmbarrier.try_wait.parity.shared.b64 p, [%1], %2;\n\tselp.b32 %0, 1, 0, p;\n\t}" \
        : "=r"(_d) : "r"(_m), "r"(_p) : "memory"); \
    if (!_d) { \
        asm volatile("{\n\t.reg .pred P1;\n\tWL_%=:\n\tmbarrier.try_wait.parity.shared.b64 P1, [%0], %1;\n\t@P1 bra.uni WD_%=;\n\tbra.uni WL_%=;\n\tWD_%=:\n\t}" \
            :: "r"(_m), "r"(_p) : "memory"); \
    } } while (0)

__device__ __forceinline__ uint32_t lds_u32(uint32_t a) {
    uint32_t v; asm volatile("ld.shared.b32 %0, [%1];" : "=r"(v) : "r"(a)); return v;
}
__device__ __forceinline__ uint2 lds_u64(uint32_t a) {
    uint2 v; asm volatile("ld.shared.v2.u32 {%0,%1}, [%2];" : "=r"(v.x), "=r"(v.y) : "r"(a)); return v;
}

#define MMA_F16(c, a0, a1, a2, a3, b0, b1) \
    asm volatile("mma.sync.aligned.m16n8k16.row.col.f32.f16.f16.f32 " \
        "{%0,%1,%2,%3}, {%4,%5,%6,%7}, {%8,%9}, {%0,%1,%2,%3};" \
        : "+f"((c)[0]), "+f"((c)[1]), "+f"((c)[2]), "+f"((c)[3]) \
        : "r"(a0), "r"(a1), "r"(a2), "r"(a3), "r"(b0), "r"(b1))

// ===================== K1: projection + node tables + counter reset =====================
__global__ __launch_bounds__(256) void k_proj(const float* __restrict__ X,
                                              const float* __restrict__ W,
                                              const float* __restrict__ a1,
                                              const float* __restrict__ a2) {
    __shared__ float Ws[FIN * FOUT];
    __shared__ float Xs[FIN * 17];
    __shared__ uint16_t hTs[FOUT * 20];

    const int tid = threadIdx.x;
    const int i0 = blockIdx.x * 16;

    if (blockIdx.x == 0 && tid < NN / TI) g_cnt[tid] = 0;

    {
        const float4* W4 = (const float4*)W;
        float4* Ws4 = (float4*)Ws;
#pragma unroll
        for (int k = 0; k < 8; k++) Ws4[tid + k * 256] = W4[tid + k * 256];
    }
    {
        const int row = tid & 15;
        const int q0 = tid >> 4;
#pragma unroll
        for (int m = 0; m < 2; m++) {
            const int q = q0 + 16 * m;
            const float4 v = *(const float4*)(X + (size_t)(i0 + row) * FIN + 4 * q);
            Xs[(4 * q + 0) * 17 + row] = v.x;
            Xs[(4 * q + 1) * 17 + row] = v.y;
            Xs[(4 * q + 2) * 17 + row] = v.z;
            Xs[(4 * q + 3) * 17 + row] = v.w;
        }
    }
    __syncthreads();

    const int rg = tid >> 4;
    const int cg = tid & 15;
    const float4* Ws4 = (const float4*)Ws;

    float aA[4] = {0.f, 0.f, 0.f, 0.f}, aB[4] = {0.f, 0.f, 0.f, 0.f};
#pragma unroll 8
    for (int k = 0; k < FIN; k += 2) {
        const float x0 = Xs[k * 17 + rg];
        const float x1 = Xs[(k + 1) * 17 + rg];
        const float4 w0 = Ws4[k * 16 + cg];
        const float4 w1 = Ws4[(k + 1) * 16 + cg];
        aA[0] += x0 * w0.x; aA[1] += x0 * w0.y; aA[2] += x0 * w0.z; aA[3] += x0 * w0.w;
        aB[0] += x1 * w1.x; aB[1] += x1 * w1.y; aB[2] += x1 * w1.z; aB[3] += x1 * w1.w;
    }
    float acc[4];
#pragma unroll
    for (int c = 0; c < 4; c++) acc[c] = aA[c] + aB[c];

#pragma unroll
    for (int c = 0; c < 4; c++) hTs[(4 * cg + c) * 20 + rg] = f2h(acc[c]);

    const float4 a1v = ((const float4*)a1)[cg];
    const float4 a2v = ((const float4*)a2)[cg];
    float v1 = acc[0] * a1v.x + acc[1] * a1v.y + acc[2] * a1v.z + acc[3] * a1v.w;
    float v2 = acc[0] * a2v.x + acc[1] * a2v.y + acc[2] * a2v.z + acc[3] * a2v.w;
#pragma unroll
    for (int s = 8; s > 0; s >>= 1) {
        v1 += __shfl_xor_sync(0xffffffffu, v1, s, 16);
        v2 += __shfl_xor_sync(0xffffffffu, v2, s, 16);
    }

    const float s1L = v1 * LOG2E;
    const float s2L = v2 * LOG2E;
    const float E1 = ex2f(s1L), F1 = ex2f(ALPHA * s1L);
    const float E2 = ex2f(s2L), F2 = ex2f(ALPHA * s2L);
    const float E2o = __shfl_xor_sync(0xffffffffu, E2, 16);
    const float F2o = __shfl_xor_sync(0xffffffffu, F2, 16);
    if (cg == 0) {
        g_EF1p[i0 + rg] = make_uint2(pkh2(E1, E1), pkh2(F1, F1));
        if ((tid & 31) == 0)
            g_E2Fp[(i0 + rg) >> 1] = make_uint2(pkh2(E2, E2o), pkh2(F2, F2o));
    }
    __syncthreads();

    {
        const int f = tid >> 2;
        const int sg = tid & 3;
        const uint2 v = *(const uint2*)&hTs[f * 20 + 4 * sg];
        *(uint2*)(g_hT16 + (size_t)f * NN + i0 + 4 * sg) = v;
    }
}

// ===================== K2: warp-specialized GAT; A via register-prefetched LDG =====================
__global__ __launch_bounds__(NTHREADS, 2) void k_gat(const int* __restrict__ A,
                                                     float* __restrict__ out) {
    extern __shared__ char sm[];
    const uint32_t sb0 = smem_u32(sm);
    const uint32_t sb = (sb0 + 127u) & ~127u;
    const uint32_t mb = sb + MBAR_OFF;        // full[s]=mb+s*16, empty[s]=mb+s*16+8

    const int tid  = threadIdx.x;
    const int wid  = tid >> 5;
    const int lane = tid & 31;
    const int ib   = blockIdx.x >> 2;
    const int sk   = blockIdx.x & 3;
    const int i0   = ib * TI;
    const int j0   = sk * JH;

    if (tid == 0) {
#pragma unroll
        for (int s = 0; s < NSTAGE; s++) {
            MBAR_INIT(mb + s * 16,     32);   // full: 32 producer threads
            MBAR_INIT(mb + s * 16 + 8, 8);    // empty: 8 consumer warps
        }
    }
    __syncthreads();

    if (wid == 8) {
        // ================= PRODUCER (1 warp): B + EF only =================
        const int p = lane;
        const uint16_t* hSrc = g_hT16 + j0;

        for (int t = 0; t < NCH; t++) {
            const int s = t & (NSTAGE - 1);
            const int k = t >> NSTAGE_LOG2;
            if (k > 0) MBAR_WAIT(mb + s * 16 + 8, (k - 1) & 1);

            const uint32_t base = sb + (uint32_t)(s * STAGE_BYTES);
            const int jo = t * KC;
            // B: 64 f-rows x 64B; thread covers rows p, p+32; 4 segs each
#pragma unroll
            for (int m = 0; m < 2; m++) {
                const int row = p + 32 * m;
#pragma unroll
                for (int g = 0; g < 4; g++) {
                    CP16(base + (uint32_t)(row * B_STRIDE + g * 8) * 2,
                         hSrc + (size_t)row * NN + jo + g * 8);
                }
            }
            // EF: 128B
            if (p < 8)
                CP16(base + B_BUF + (uint32_t)p * 16,
                     g_E2Fp + ((j0 + jo) >> 1) + p * 2);
            CPASYNC_MBAR_ARRIVE(mb + s * 16);
        }
    } else {
        // ================= CONSUMER (8 warps, m16 x n64 each) =================
        const int qr = lane >> 2;
        const int qc = lane & 3;
        const int w  = wid;

        const uint2 e1a = g_EF1p[i0 + w * 16 + qr];
        const uint2 e1b = g_EF1p[i0 + w * 16 + qr + 8];

        // A row pointers for this lane (rows w*16+qr and +8, col base 2*qc)
        const int* aRow0 = A + (size_t)(i0 + w * 16 + qr) * NN + j0 + 2 * qc;
        const int* aRow1 = aRow0 + (size_t)8 * NN;

        float acc[8][4];
        float accO[4];
#pragma unroll
        for (int nt = 0; nt < 8; nt++)
#pragma unroll
            for (int k = 0; k < 4; k++) acc[nt][k] = 0.f;
#pragma unroll
        for (int k = 0; k < 4; k++) accO[k] = 0.f;
        const uint32_t kOnes = 0x3C003C00u;

        // A register prefetch ping-pong: [buf][ks*4 + {Al0,Ah0,Al1,Ah1}]
        int2 aBuf[2][8];
#define LOAD_A(buf, T) do {                                        \
            const int _o = (T) * KC;                               \
            (buf)[0] = ldcs2(aRow0 + _o);                          \
            (buf)[1] = ldcs2(aRow0 + _o + 8);                      \
            (buf)[2] = ldcs2(aRow1 + _o);                          \
            (buf)[3] = ldcs2(aRow1 + _o + 8);                      \
            (buf)[4] = ldcs2(aRow0 + _o + 16);                     \
            (buf)[5] = ldcs2(aRow0 + _o + 24);                     \
            (buf)[6] = ldcs2(aRow1 + _o + 16);                     \
            (buf)[7] = ldcs2(aRow1 + _o + 24);                     \
        } while (0)

        LOAD_A(aBuf[0], 0);

#pragma unroll 2
        for (int t = 0; t < NCH; t++) {
            const int cur = t & 1;
            if (t + 1 < NCH) LOAD_A(aBuf[cur ^ 1], t + 1);

            const int s = t & (NSTAGE - 1);
            const int k = t >> NSTAGE_LOG2;
            MBAR_WAIT(mb + s * 16, k & 1);

            const uint32_t bB = sb + (uint32_t)(s * STAGE_BYTES);
            const uint32_t eB = bB + B_BUF;

#pragma unroll
            for (int ks = 0; ks < 2; ks++) {
                const int j2 = 16 * ks + 2 * qc;
                const uint2 efL = lds_u64(eB + (uint32_t)(8 * ks + qc) * 8);
                const uint2 efH = lds_u64(eB + (uint32_t)(8 * ks + qc + 4) * 8);

                uint32_t b0[8], b1[8];
#pragma unroll
                for (int nt = 0; nt < 8; nt++) {
                    const uint32_t hb = bB + (uint32_t)((nt * 8 + qr) * B_STRIDE + j2) * 2;
                    b0[nt] = lds_u32(hb);
                    b1[nt] = lds_u32(hb + 16);
                }

                const int2 Al0 = aBuf[cur][ks * 4 + 0];
                const int2 Ah0 = aBuf[cur][ks * 4 + 1];
                const int2 Al1 = aBuf[cur][ks * 4 + 2];
                const int2 Ah1 = aBuf[cur][ks * 4 + 3];

                const uint32_t a0 = wpair(e1a.x, e1a.y, efL.x, efL.y, Al0.x, Al0.y);
                const uint32_t a1 = wpair(e1b.x, e1b.y, efL.x, efL.y, Al1.x, Al1.y);
                const uint32_t a2 = wpair(e1a.x, e1a.y, efH.x, efH.y, Ah0.x, Ah0.y);
                const uint32_t a3 = wpair(e1b.x, e1b.y, efH.x, efH.y, Ah1.x, Ah1.y);

#pragma unroll
                for (int nt = 0; nt < 8; nt++)
                    MMA_F16(acc[nt], a0, a1, a2, a3, b0[nt], b1[nt]);
                MMA_F16(accO, a0, a1, a2, a3, kOnes, kOnes);
            }
            __syncwarp();
            if (lane == 0) MBAR_ARRIVE(mb + s * 16 + 8);
        }

        // ---- epilogue: store partials ----
        if (qc == 0) {
            g_wsum[sk][i0 + w * 16 + qr]     = accO[0];
            g_wsum[sk][i0 + w * 16 + qr + 8] = accO[2];
        }
        float* pr0 = &g_part[sk][(size_t)(i0 + w * 16 + qr) * FOUT];
        float* pr1 = &g_part[sk][(size_t)(i0 + w * 16 + qr + 8) * FOUT];
#pragma unroll
        for (int nt = 0; nt < 8; nt++) {
            const int c0 = nt * 8 + 2 * qc;
            *(float2*)(pr0 + c0) = make_float2(acc[nt][0], acc[nt][1]);
            *(float2*)(pr1 + c0) = make_float2(acc[nt][2], acc[nt][3]);
        }
    }

    // ---- last split-K CTA for this i-block combines and divides ----
    __threadfence();
    __syncthreads();
    __shared__ int isLast;
    if (tid == 0) isLast = (atomicAdd(&g_cnt[ib], 1) == SPLIT - 1) ? 1 : 0;
    __syncthreads();
    if (isLast && tid < 256) {
        __threadfence();
#pragma unroll
        for (int k = 0; k < 8; k++) {
            const int idx4 = tid + k * 256;
            const int row = idx4 >> 4;
            const size_t e = (size_t)(i0 + row) * FOUT + (idx4 & 15) * 4;
            float4 s = *(const float4*)&g_part[0][e];
            float den = g_wsum[0][i0 + row];
#pragma unroll
            for (int p = 1; p < SPLIT; p++) {
                const float4 pp = *(const float4*)&g_part[p][e];
                s.x += pp.x; s.y += pp.y; s.z += pp.z; s.w += pp.w;
                den += g_wsum[p][i0 + row];
            }
            const float inv = 1.0f / den;
            *(float4*)(out + e) = make_float4(s.x * inv, s.y * inv, s.z * inv, s.w * inv);
        }
    }
}

extern "C" void kernel_launch(void* const* d_in, const int* in_sizes, int n_in,
                              void* d_out, int out_size) {
    const float* X  = (const float*)d_in[0];
    const int*   A  = (const int*)d_in[1];
    const float* W  = (const float*)d_in[2];
    const float* a1 = (const float*)d_in[3];
    const float* a2 = (const float*)d_in[4];
    float* out = (float*)d_out;

    cudaFuncSetAttribute(k_gat, cudaFuncAttributeMaxDynamicSharedMemorySize, GAT_SMEM);

    k_proj<<<NN / 16, 256>>>(X, W, a1, a2);
    k_gat<<<(NN / TI) * SPLIT, NTHREADS, GAT_SMEM>>>(A, out);
}